// round 1
// baseline (speedup 1.0000x reference)
#include <cuda_runtime.h>
#include <math.h>

// Problem constants
#define Bc   8
#define Cc   128
#define Hd   128
#define Wd   128
#define HW   16384          // Hd*Wd
#define NH   8

// ---------------- scratch (static device memory; no allocations) ------------
__device__ float g_t  [(size_t)Bc * 384 * HW];   // pos-conv output (B,384,HW)
__device__ float g_qkv[(size_t)Bc * 384 * HW];   // concat(qd3,qd5)  (B,384,HW)
__device__ float g_y  [(size_t)Bc * 256 * HW];   // concat(out,d3,d5)(B,256,HW)
__device__ float g_ssq[Bc * 256];                // sum of squares for q,k channels
__device__ float g_gram[8 * 64 * 256];           // 8 n-chunk partials of 16x16 grams
__device__ float g_attn[64 * 256];               // softmaxed attention (bh, d, e)

// ---------------- 1x1 conv as batched GEMM ----------------------------------
// C[b,m,n] = sum_k A[m,k] * X[b,k,n] (+ bias[m])
// MODE 0: X = external (x input), C = g_t      (M=384,K=128, bias=pos_b)
// MODE 1: X = g_y,                C = external (M=128,K=256, no bias)
template<int M, int K, int MODE>
__global__ void __launch_bounds__(256) gemm1x1(const float* __restrict__ A,
                                               const float* __restrict__ Xext,
                                               const float* __restrict__ bias,
                                               float* __restrict__ Cext)
{
    const float* X = (MODE == 0) ? Xext : g_y;
    float*       C = (MODE == 0) ? g_t  : Cext;

    const int b  = blockIdx.z;
    const int m0 = blockIdx.y * 64;
    const int n0 = blockIdx.x * 64;

    __shared__ float As[16][64];
    __shared__ float Xs[16][64];

    const int t  = threadIdx.x;
    const int ty = t >> 4;       // 0..15
    const int tx = t & 15;       // 0..15

    float acc[4][4];
#pragma unroll
    for (int i = 0; i < 4; i++)
#pragma unroll
        for (int j = 0; j < 4; j++) acc[i][j] = 0.f;

    const float* Xb = X + (size_t)b * K * HW;

    const int arow = t >> 2;          // 0..63
    const int akc  = (t & 3) * 4;     // 0,4,8,12
    const int xrow = t >> 4;          // 0..15
    const int xnc  = (t & 15) * 4;    // 0..60

    for (int k0 = 0; k0 < K; k0 += 16) {
        // A tile: 64 m x 16 k, stored transposed
        float4 a4 = *(const float4*)(A + (size_t)(m0 + arow) * K + k0 + akc);
        As[akc + 0][arow] = a4.x;
        As[akc + 1][arow] = a4.y;
        As[akc + 2][arow] = a4.z;
        As[akc + 3][arow] = a4.w;
        // X tile: 16 k x 64 n
        *(float4*)&Xs[xrow][xnc] =
            *(const float4*)(Xb + (size_t)(k0 + xrow) * HW + n0 + xnc);
        __syncthreads();

#pragma unroll
        for (int kk = 0; kk < 16; kk++) {
            float a[4], xv[4];
#pragma unroll
            for (int i = 0; i < 4; i++) a[i]  = As[kk][ty * 4 + i];
#pragma unroll
            for (int j = 0; j < 4; j++) xv[j] = Xs[kk][tx * 4 + j];
#pragma unroll
            for (int i = 0; i < 4; i++)
#pragma unroll
                for (int j = 0; j < 4; j++) acc[i][j] += a[i] * xv[j];
        }
        __syncthreads();
    }

#pragma unroll
    for (int i = 0; i < 4; i++) {
        const int m = m0 + ty * 4 + i;
        const float bb = bias ? bias[m] : 0.f;
        float4 r = make_float4(acc[i][0] + bb, acc[i][1] + bb,
                               acc[i][2] + bb, acc[i][3] + bb);
        *(float4*)(C + ((size_t)b * M + m) * HW + n0 + tx * 4) = r;
    }
}

// ---------------- dual grouped conv (3x3 pad1 + 5x5 pad2, 2 in-ch/group) ----
// MODE 0: in = g_t (Cin=384), out = g_qkv (TotC=384, 3x3 at ch g, 5x5 at 192+g)
// MODE 1: in = x   (Cin=128), out = g_y   (TotC=256, 3x3 at 128+g, 5x5 at 192+g)
template<int MODE>
__global__ void __launch_bounds__(256) dualconv(const float* __restrict__ xin,
                                                const float* __restrict__ w3,
                                                const float* __restrict__ b3,
                                                const float* __restrict__ w5,
                                                const float* __restrict__ b5)
{
    constexpr int Cin  = MODE ? 128 : 384;
    constexpr int TotC = MODE ? 256 : 384;
    constexpr int C3B  = MODE ? 128 : 0;
    constexpr int C5B  = 192;

    const float* in  = MODE ? xin : g_t;
    float*       out = MODE ? g_y : g_qkv;

    const int g    = blockIdx.y;
    const int b    = blockIdx.z;
    const int tile = blockIdx.x;          // 0..15 (4x4 tiles of 32x32)
    const int X0 = (tile & 3) * 32;
    const int Y0 = (tile >> 2) * 32;

    __shared__ float sm[2 * 36 * 36];
    __shared__ float sw3[18], sw5[50], sb[2];

    const int t = threadIdx.x;
    if (t < 18)       sw3[t]      = w3[g * 18 + t];
    else if (t < 68)  sw5[t - 18] = w5[g * 50 + (t - 18)];
    else if (t == 68) sb[0] = b3[g];
    else if (t == 69) sb[1] = b5[g];

    const float* inb = in + ((size_t)b * Cin + 2 * g) * HW;
    for (int i = t; i < 2 * 36 * 36; i += 256) {
        int ch = i / 1296;
        int r  = i - ch * 1296;
        int y  = r / 36;
        int x  = r - y * 36;
        int gy = Y0 - 2 + y, gx = X0 - 2 + x;
        float v = 0.f;
        if ((unsigned)gy < (unsigned)Hd && (unsigned)gx < (unsigned)Wd)
            v = inb[(size_t)ch * HW + gy * Wd + gx];
        sm[i] = v;
    }
    __syncthreads();

    const int ty  = t >> 3;          // 0..31 output row
    const int txb = (t & 7) * 4;     // 4 consecutive output cols

    float a3[4], a5[4];
#pragma unroll
    for (int j = 0; j < 4; j++) { a3[j] = sb[0]; a5[j] = sb[1]; }

#pragma unroll
    for (int ch = 0; ch < 2; ch++) {
        const float* smc = sm + ch * 1296;
#pragma unroll
        for (int ky = 0; ky < 5; ky++) {
            float row[8];
            const float* rp = smc + (ty + ky) * 36 + txb;
#pragma unroll
            for (int x = 0; x < 8; x++) row[x] = rp[x];
#pragma unroll
            for (int kx = 0; kx < 5; kx++) {
                const float w = sw5[ch * 25 + ky * 5 + kx];
#pragma unroll
                for (int j = 0; j < 4; j++) a5[j] += w * row[kx + j];
            }
            if (ky >= 1 && ky <= 3) {
#pragma unroll
                for (int kx = 0; kx < 3; kx++) {
                    const float w = sw3[ch * 9 + (ky - 1) * 3 + kx];
#pragma unroll
                    for (int j = 0; j < 4; j++) a3[j] += w * row[kx + 1 + j];
                }
            }
        }
    }

    const size_t p = (size_t)(Y0 + ty) * Wd + X0 + txb;
    *(float4*)(out + ((size_t)b * TotC + C3B + g) * HW + p) =
        make_float4(a3[0], a3[1], a3[2], a3[3]);
    *(float4*)(out + ((size_t)b * TotC + C5B + g) * HW + p) =
        make_float4(a5[0], a5[1], a5[2], a5[3]);
}

// ---------------- sum of squares per (b, qkv-channel<256) -------------------
__global__ void __launch_bounds__(256) sumsq_k()
{
    const int c = blockIdx.x & 255;
    const int b = blockIdx.x >> 8;
    const float4* p4 = (const float4*)(g_qkv + ((size_t)b * 384 + c) * HW);
    float s = 0.f;
    for (int i = threadIdx.x; i < HW / 4; i += 256) {
        float4 v = p4[i];
        s += v.x * v.x + v.y * v.y + v.z * v.z + v.w * v.w;
    }
    __shared__ float red[256];
    red[threadIdx.x] = s;
    __syncthreads();
    for (int o = 128; o > 0; o >>= 1) {
        if (threadIdx.x < o) red[threadIdx.x] += red[threadIdx.x + o];
        __syncthreads();
    }
    if (threadIdx.x == 0) g_ssq[blockIdx.x] = red[0];
}

// ---------------- gram: G[bh][d][e] partials over 8 n-chunks ----------------
__global__ void __launch_bounds__(256) gram_k()
{
    const int bh    = blockIdx.x;     // 0..63
    const int b     = bh >> 3, h = bh & 7;
    const int chunk = blockIdx.y;     // 0..7  (2048 n each)

    const float* qp = g_qkv + ((size_t)b * 384 +       h * 16) * HW;
    const float* kp = g_qkv + ((size_t)b * 384 + 128 + h * 16) * HW;

    __shared__ float qs[128 * 17];
    __shared__ float ks[128 * 17];

    const int t = threadIdx.x;
    const int d = t >> 4, e = t & 15;
    float acc = 0.f;

    const int nbeg = chunk * 2048;
    for (int n0 = nbeg; n0 < nbeg + 2048; n0 += 128) {
#pragma unroll
        for (int i = 0; i < 8; i++) {
            int idx = t + i * 256;
            int cl = idx >> 7, nl = idx & 127;
            qs[nl * 17 + cl] = qp[(size_t)cl * HW + n0 + nl];
            ks[nl * 17 + cl] = kp[(size_t)cl * HW + n0 + nl];
        }
        __syncthreads();
#pragma unroll 8
        for (int n = 0; n < 128; n++)
            acc += qs[n * 17 + d] * ks[n * 17 + e];
        __syncthreads();
    }
    g_gram[((size_t)chunk * 64 + bh) * 256 + t] = acc;
}

// ---------------- softmax over e with l2-normalization + temperature --------
__global__ void __launch_bounds__(256) softmax_k(const float* __restrict__ temp)
{
    const int bh = blockIdx.x;
    const int b  = bh >> 3, h = bh & 7;
    const int t  = threadIdx.x;
    const int d  = t >> 4, e = t & 15;

    float gsum = 0.f;
#pragma unroll
    for (int c = 0; c < 8; c++) gsum += g_gram[((size_t)c * 64 + bh) * 256 + t];

    const float nq = fmaxf(sqrtf(g_ssq[b * 256 + h * 16 + d]), 1e-12f);
    const float nk = fmaxf(sqrtf(g_ssq[b * 256 + 128 + h * 16 + e]), 1e-12f);
    float logit = gsum / (nq * nk) * temp[h];

    // softmax over the 16 e-lanes (xor<16 stays within 16-lane groups)
    float m = logit;
#pragma unroll
    for (int o = 8; o > 0; o >>= 1)
        m = fmaxf(m, __shfl_xor_sync(0xffffffffu, m, o));
    float ex = expf(logit - m);
    float s = ex;
#pragma unroll
    for (int o = 8; o > 0; o >>= 1)
        s += __shfl_xor_sync(0xffffffffu, s, o);

    g_attn[bh * 256 + t] = ex / s;
}

// ---------------- out = attn @ v  -> y channels 0..127 ----------------------
__global__ void __launch_bounds__(256) av_k()
{
    const int bh = blockIdx.y;
    const int b  = bh >> 3, h = bh & 7;
    const int n  = blockIdx.x * 256 + threadIdx.x;

    __shared__ float As[256];
    As[threadIdx.x] = g_attn[bh * 256 + threadIdx.x];
    __syncthreads();

    const float* vp = g_qkv + ((size_t)b * 384 + 256 + h * 16) * HW + n;
    float acc[16];
#pragma unroll
    for (int d = 0; d < 16; d++) acc[d] = 0.f;
#pragma unroll
    for (int e = 0; e < 16; e++) {
        const float v = vp[(size_t)e * HW];
#pragma unroll
        for (int d = 0; d < 16; d++) acc[d] += As[d * 16 + e] * v;
    }
    float* yp = g_y + ((size_t)b * 256 + h * 16) * HW + n;
#pragma unroll
    for (int d = 0; d < 16; d++) yp[(size_t)d * HW] = acc[d];
}

// ---------------- launcher ---------------------------------------------------
extern "C" void kernel_launch(void* const* d_in, const int* in_sizes, int n_in,
                              void* d_out, int out_size)
{
    const float* x      = (const float*)d_in[0];
    const float* pos_w  = (const float*)d_in[1];
    const float* pos_b  = (const float*)d_in[2];
    const float* qd3_w  = (const float*)d_in[3];
    const float* qd3_b  = (const float*)d_in[4];
    const float* qd5_w  = (const float*)d_in[5];
    const float* qd5_b  = (const float*)d_in[6];
    const float* temp   = (const float*)d_in[7];
    const float* d3_w   = (const float*)d_in[8];
    const float* d3_b   = (const float*)d_in[9];
    const float* d5_w   = (const float*)d_in[10];
    const float* d5_b   = (const float*)d_in[11];
    const float* proj_w = (const float*)d_in[12];
    float* out = (float*)d_out;

    // 1) t = pos 1x1 conv:  (384,128) @ x
    gemm1x1<384, 128, 0><<<dim3(HW / 64, 384 / 64, Bc), 256>>>(pos_w, x, pos_b, nullptr);

    // 2) qkv = concat(qd3(t), qd5(t))  (grouped, 2 in-ch per group)
    dualconv<0><<<dim3(16, 192, Bc), 256>>>(nullptr, qd3_w, qd3_b, qd5_w, qd5_b);

    // 3) per-(b, channel<256) sum of squares (for l2 norms of q and k)
    sumsq_k<<<Bc * 256, 256>>>();

    // 4) gram partials, 8 n-chunks
    gram_k<<<dim3(64, 8), 256>>>();

    // 5) normalize + temperature + softmax -> attn
    softmax_k<<<64, 256>>>(temp);

    // 6) y[0:128] = attn @ v
    av_k<<<dim3(HW / 256, 64), 256>>>();

    // 7) y[128:256] = concat(d3(x), d5(x))
    dualconv<1><<<dim3(16, 64, Bc), 256>>>(x, d3_w, d3_b, d5_w, d5_b);

    // 8) result = proj 1x1 conv: (128,256) @ y
    gemm1x1<128, 256, 1><<<dim3(HW / 64, 128 / 64, Bc), 256>>>(proj_w, nullptr, nullptr, out);
}

// round 2
// speedup vs baseline: 1.1324x; 1.1324x over previous
#include <cuda_runtime.h>
#include <math.h>

// Problem constants
#define Bc   8
#define Cc   128
#define Hd   128
#define Wd   128
#define HW   16384          // Hd*Wd
#define NH   8

typedef unsigned long long ull;

__device__ __forceinline__ ull fma2(ull a, ull b, ull c) {
    ull d;
    asm("fma.rn.f32x2 %0, %1, %2, %3;" : "=l"(d) : "l"(a), "l"(b), "l"(c));
    return d;
}

// ---------------- scratch (static device memory; no allocations) ------------
__device__ float g_t  [(size_t)Bc * 384 * HW];   // pos-conv output (B,384,HW)
__device__ float g_qkv[(size_t)Bc * 384 * HW];   // concat(qd3,qd5)  (B,384,HW)
__device__ float g_y  [(size_t)Bc * 256 * HW];   // concat(out,d3,d5)(B,256,HW)
__device__ float g_ssqp[8 * 64 * 32];            // [chunk][bh][16 q + 16 k] ssq partials
__device__ float g_gram[8 * 64 * 256];           // 8 n-chunk partials of 16x16 grams
__device__ float g_attn[64 * 256];               // softmaxed attention (bh, d, e)

// ---------------- 1x1 conv as batched GEMM (f32x2 / FFMA2) ------------------
// C[b,m,n] = sum_k A[m,k] * X[b,k,n] (+ bias[m])
// Block tile 128(m) x 128(n) x 16(k), 256 threads, 8x8 per thread.
// MODE 0: X = external (x input), C = g_t      (M=384,K=128, bias=pos_b)
// MODE 1: X = g_y,                C = external (M=128,K=256, no bias)
template<int M, int K, int MODE>
__global__ void __launch_bounds__(256, 2) gemm_f2(const float* __restrict__ A,
                                                  const float* __restrict__ Xext,
                                                  const float* __restrict__ bias,
                                                  float* __restrict__ Cext)
{
    const float* X = (MODE == 0) ? Xext : g_y;
    float*       C = (MODE == 0) ? g_t  : Cext;

    const int b  = blockIdx.z;
    const int m0 = blockIdx.y * 128;
    const int n0 = blockIdx.x * 128;

    __shared__ float Asd[16][256];   // duplicated: Asd[k][2m] = Asd[k][2m+1] = A[m0+m][k0+k]
    __shared__ float Xs [16][128];

    const int t   = threadIdx.x;
    const int tym = t >> 4;          // 0..15  -> m = tym*8 .. +7
    const int txn = t & 15;          // 0..15  -> n = 2*txn + 32*j (+0/1), j=0..3

    ull acc[8][4];
#pragma unroll
    for (int i = 0; i < 8; i++)
#pragma unroll
        for (int j = 0; j < 4; j++) acc[i][j] = 0ull;

    const float* Xb = X + (size_t)b * K * HW + n0;
    const float* Ab = A + (size_t)(m0 + (t >> 1)) * K + (t & 1) * 8;

    const int xk = t >> 5;           // 0..7
    const int xn = (t & 31) * 4;     // 0..124

    for (int k0 = 0; k0 < K; k0 += 16) {
        // A tile: thread loads 8 consecutive k of row m=(t>>1), stores duplicated
        {
            float4 a0 = *(const float4*)(Ab + k0);
            float4 a1 = *(const float4*)(Ab + k0 + 4);
            const int m2 = (t >> 1) * 2;
            const int kq = (t & 1) * 8;
            *(float2*)&Asd[kq + 0][m2] = make_float2(a0.x, a0.x);
            *(float2*)&Asd[kq + 1][m2] = make_float2(a0.y, a0.y);
            *(float2*)&Asd[kq + 2][m2] = make_float2(a0.z, a0.z);
            *(float2*)&Asd[kq + 3][m2] = make_float2(a0.w, a0.w);
            *(float2*)&Asd[kq + 4][m2] = make_float2(a1.x, a1.x);
            *(float2*)&Asd[kq + 5][m2] = make_float2(a1.y, a1.y);
            *(float2*)&Asd[kq + 6][m2] = make_float2(a1.z, a1.z);
            *(float2*)&Asd[kq + 7][m2] = make_float2(a1.w, a1.w);
        }
        // X tile: 16 k x 128 n
        *(float4*)&Xs[xk    ][xn] = *(const float4*)(Xb + (size_t)(k0 + xk    ) * HW + xn);
        *(float4*)&Xs[xk + 8][xn] = *(const float4*)(Xb + (size_t)(k0 + xk + 8) * HW + xn);
        __syncthreads();

#pragma unroll
        for (int kk = 0; kk < 16; kk++) {
            ull a2[8], x2[4];
#pragma unroll
            for (int i = 0; i < 8; i++)
                a2[i] = *(const ull*)&Asd[kk][(tym * 8 + i) * 2];
#pragma unroll
            for (int j = 0; j < 4; j++)
                x2[j] = *(const ull*)&Xs[kk][32 * j + 2 * txn];
#pragma unroll
            for (int i = 0; i < 8; i++)
#pragma unroll
                for (int j = 0; j < 4; j++)
                    acc[i][j] = fma2(a2[i], x2[j], acc[i][j]);
        }
        __syncthreads();
    }

#pragma unroll
    for (int i = 0; i < 8; i++) {
        const int m = m0 + tym * 8 + i;
        const float bb = (MODE == 0) ? bias[m] : 0.f;
        float* Crow = C + ((size_t)b * M + m) * HW + n0 + 2 * txn;
#pragma unroll
        for (int j = 0; j < 4; j++) {
            float2 v = *(float2*)&acc[i][j];
            v.x += bb; v.y += bb;
            *(float2*)(Crow + 32 * j) = v;
        }
    }
}

// ---------------- dual grouped conv (3x3 pad1 + 5x5 pad2, 2 in-ch/group) ----
template<int MODE>
__global__ void __launch_bounds__(256) dualconv(const float* __restrict__ xin,
                                                const float* __restrict__ w3,
                                                const float* __restrict__ b3,
                                                const float* __restrict__ w5,
                                                const float* __restrict__ b5)
{
    constexpr int Cin  = MODE ? 128 : 384;
    constexpr int TotC = MODE ? 256 : 384;
    constexpr int C3B  = MODE ? 128 : 0;
    constexpr int C5B  = 192;

    const float* in  = MODE ? xin : g_t;
    float*       out = MODE ? g_y : g_qkv;

    const int g    = blockIdx.y;
    const int b    = blockIdx.z;
    const int tile = blockIdx.x;          // 0..15 (4x4 tiles of 32x32)
    const int X0 = (tile & 3) * 32;
    const int Y0 = (tile >> 2) * 32;

    __shared__ float sm[2 * 36 * 36];
    __shared__ float sw3[18], sw5[50], sb[2];

    const int t = threadIdx.x;
    if (t < 18)       sw3[t]      = w3[g * 18 + t];
    else if (t < 68)  sw5[t - 18] = w5[g * 50 + (t - 18)];
    else if (t == 68) sb[0] = b3[g];
    else if (t == 69) sb[1] = b5[g];

    const float* inb = in + ((size_t)b * Cin + 2 * g) * HW;
    for (int i = t; i < 2 * 36 * 36; i += 256) {
        int ch = i / 1296;
        int r  = i - ch * 1296;
        int y  = r / 36;
        int x  = r - y * 36;
        int gy = Y0 - 2 + y, gx = X0 - 2 + x;
        float v = 0.f;
        if ((unsigned)gy < (unsigned)Hd && (unsigned)gx < (unsigned)Wd)
            v = inb[(size_t)ch * HW + gy * Wd + gx];
        sm[i] = v;
    }
    __syncthreads();

    const int ty  = t >> 3;          // 0..31 output row
    const int txb = (t & 7) * 4;     // 4 consecutive output cols

    float a3[4], a5[4];
#pragma unroll
    for (int j = 0; j < 4; j++) { a3[j] = sb[0]; a5[j] = sb[1]; }

#pragma unroll
    for (int ch = 0; ch < 2; ch++) {
        const float* smc = sm + ch * 1296;
#pragma unroll
        for (int ky = 0; ky < 5; ky++) {
            float row[8];
            const float* rp = smc + (ty + ky) * 36 + txb;
#pragma unroll
            for (int x = 0; x < 8; x++) row[x] = rp[x];
#pragma unroll
            for (int kx = 0; kx < 5; kx++) {
                const float w = sw5[ch * 25 + ky * 5 + kx];
#pragma unroll
                for (int j = 0; j < 4; j++) a5[j] += w * row[kx + j];
            }
            if (ky >= 1 && ky <= 3) {
#pragma unroll
                for (int kx = 0; kx < 3; kx++) {
                    const float w = sw3[ch * 9 + (ky - 1) * 3 + kx];
#pragma unroll
                    for (int j = 0; j < 4; j++) a3[j] += w * row[kx + 1 + j];
                }
            }
        }
    }

    const size_t p = (size_t)(Y0 + ty) * Wd + X0 + txb;
    *(float4*)(out + ((size_t)b * TotC + C3B + g) * HW + p) =
        make_float4(a3[0], a3[1], a3[2], a3[3]);
    *(float4*)(out + ((size_t)b * TotC + C5B + g) * HW + p) =
        make_float4(a5[0], a5[1], a5[2], a5[3]);
}

// ---------------- gram + fused ssq: G[bh][d][e] partials over 8 n-chunks ----
// Tiles stored [c][n] (no transpose). ssq accumulated during loads.
__global__ void __launch_bounds__(256) gram_k()
{
    const int bh    = blockIdx.x;     // 0..63
    const int b     = bh >> 3, h = bh & 7;
    const int chunk = blockIdx.y;     // 0..7  (2048 n each)

    const float* qp = g_qkv + ((size_t)b * 384 +       h * 16) * HW;
    const float* kp = g_qkv + ((size_t)b * 384 + 128 + h * 16) * HW;

    __shared__ float qs[16][132];
    __shared__ float ks[16][132];

    const int t = threadIdx.x;
    const int d = t >> 4, e = t & 15;

    // load indexing: idx = t + r*256 ; cl = idx>>5 (constant per warp), nl=(idx&31)*4
    const int cl0 = t >> 5;           // 0..7
    const int nl0 = (t & 31) * 4;

    ull acc_a = 0, acc_b = 0;
    ull sq_q0 = 0, sq_q1 = 0, sq_k0 = 0, sq_k1 = 0;

    const int nbeg = chunk * 2048;
    for (int n0 = nbeg; n0 < nbeg + 2048; n0 += 128) {
        float4 q0 = *(const float4*)(qp + (size_t)cl0 * HW + n0 + nl0);
        float4 q1 = *(const float4*)(qp + (size_t)(cl0 + 8) * HW + n0 + nl0);
        float4 k0 = *(const float4*)(kp + (size_t)cl0 * HW + n0 + nl0);
        float4 k1 = *(const float4*)(kp + (size_t)(cl0 + 8) * HW + n0 + nl0);
        // fused sum-of-squares
        ull* q0p = (ull*)&q0; ull* q1p = (ull*)&q1;
        ull* k0p = (ull*)&k0; ull* k1p = (ull*)&k1;
        sq_q0 = fma2(q0p[0], q0p[0], sq_q0); sq_q0 = fma2(q0p[1], q0p[1], sq_q0);
        sq_q1 = fma2(q1p[0], q1p[0], sq_q1); sq_q1 = fma2(q1p[1], q1p[1], sq_q1);
        sq_k0 = fma2(k0p[0], k0p[0], sq_k0); sq_k0 = fma2(k0p[1], k0p[1], sq_k0);
        sq_k1 = fma2(k1p[0], k1p[0], sq_k1); sq_k1 = fma2(k1p[1], k1p[1], sq_k1);

        *(float4*)&qs[cl0    ][nl0] = q0;
        *(float4*)&qs[cl0 + 8][nl0] = q1;
        *(float4*)&ks[cl0    ][nl0] = k0;
        *(float4*)&ks[cl0 + 8][nl0] = k1;
        __syncthreads();

#pragma unroll 8
        for (int n = 0; n < 128; n += 4) {
            ull q01 = *(const ull*)&qs[d][n];
            ull q23 = *(const ull*)&qs[d][n + 2];
            ull k01 = *(const ull*)&ks[e][n];
            ull k23 = *(const ull*)&ks[e][n + 2];
            acc_a = fma2(q01, k01, acc_a);
            acc_b = fma2(q23, k23, acc_b);
        }
        __syncthreads();
    }

    {
        float2 pa = *(float2*)&acc_a, pb = *(float2*)&acc_b;
        g_gram[((size_t)chunk * 64 + bh) * 256 + t] = pa.x + pa.y + pb.x + pb.y;
    }

    // warp-reduce ssq partials: channel (cl0) and (cl0+8) for q and k
    float2 a;
    a = *(float2*)&sq_q0; float vq0 = a.x + a.y;
    a = *(float2*)&sq_q1; float vq1 = a.x + a.y;
    a = *(float2*)&sq_k0; float vk0 = a.x + a.y;
    a = *(float2*)&sq_k1; float vk1 = a.x + a.y;
#pragma unroll
    for (int o = 16; o > 0; o >>= 1) {
        vq0 += __shfl_xor_sync(0xffffffffu, vq0, o);
        vq1 += __shfl_xor_sync(0xffffffffu, vq1, o);
        vk0 += __shfl_xor_sync(0xffffffffu, vk0, o);
        vk1 += __shfl_xor_sync(0xffffffffu, vk1, o);
    }
    if ((t & 31) == 0) {
        float* dst = g_ssqp + ((size_t)chunk * 64 + bh) * 32;
        dst[cl0]          = vq0;
        dst[cl0 + 8]      = vq1;
        dst[16 + cl0]     = vk0;
        dst[16 + cl0 + 8] = vk1;
    }
}

// ---------------- softmax over e with l2-normalization + temperature --------
__global__ void __launch_bounds__(256) softmax_k(const float* __restrict__ temp)
{
    const int bh = blockIdx.x;
    const int h  = bh & 7;
    const int t  = threadIdx.x;
    const int d  = t >> 4, e = t & 15;

    float gsum = 0.f, sq = 0.f, sk = 0.f;
#pragma unroll
    for (int c = 0; c < 8; c++) {
        gsum += g_gram[((size_t)c * 64 + bh) * 256 + t];
        sq   += g_ssqp[((size_t)c * 64 + bh) * 32 + d];
        sk   += g_ssqp[((size_t)c * 64 + bh) * 32 + 16 + e];
    }

    const float nq = fmaxf(sqrtf(sq), 1e-12f);
    const float nk = fmaxf(sqrtf(sk), 1e-12f);
    float logit = gsum / (nq * nk) * temp[h];

    float m = logit;
#pragma unroll
    for (int o = 8; o > 0; o >>= 1)
        m = fmaxf(m, __shfl_xor_sync(0xffffffffu, m, o));
    float ex = expf(logit - m);
    float s = ex;
#pragma unroll
    for (int o = 8; o > 0; o >>= 1)
        s += __shfl_xor_sync(0xffffffffu, s, o);

    g_attn[bh * 256 + t] = ex / s;
}

// ---------------- out = attn @ v  -> y channels 0..127 (4n per thread) ------
__global__ void __launch_bounds__(256) av_k()
{
    const int bh = blockIdx.y;
    const int b  = bh >> 3, h = bh & 7;
    const int n  = blockIdx.x * 1024 + threadIdx.x * 4;

    __shared__ float As[256];
    As[threadIdx.x] = g_attn[bh * 256 + threadIdx.x];
    __syncthreads();

    const float* vp = g_qkv + ((size_t)b * 384 + 256 + h * 16) * HW + n;
    float acc[16][4];
#pragma unroll
    for (int dd = 0; dd < 16; dd++)
#pragma unroll
        for (int c = 0; c < 4; c++) acc[dd][c] = 0.f;

#pragma unroll
    for (int e = 0; e < 16; e++) {
        const float4 v4 = *(const float4*)(vp + (size_t)e * HW);
#pragma unroll
        for (int dd = 0; dd < 16; dd++) {
            const float w = As[dd * 16 + e];
            acc[dd][0] += w * v4.x;
            acc[dd][1] += w * v4.y;
            acc[dd][2] += w * v4.z;
            acc[dd][3] += w * v4.w;
        }
    }
    float* yp = g_y + ((size_t)b * 256 + h * 16) * HW + n;
#pragma unroll
    for (int dd = 0; dd < 16; dd++)
        *(float4*)(yp + (size_t)dd * HW) =
            make_float4(acc[dd][0], acc[dd][1], acc[dd][2], acc[dd][3]);
}

// ---------------- launcher ---------------------------------------------------
extern "C" void kernel_launch(void* const* d_in, const int* in_sizes, int n_in,
                              void* d_out, int out_size)
{
    const float* x      = (const float*)d_in[0];
    const float* pos_w  = (const float*)d_in[1];
    const float* pos_b  = (const float*)d_in[2];
    const float* qd3_w  = (const float*)d_in[3];
    const float* qd3_b  = (const float*)d_in[4];
    const float* qd5_w  = (const float*)d_in[5];
    const float* qd5_b  = (const float*)d_in[6];
    const float* temp   = (const float*)d_in[7];
    const float* d3_w   = (const float*)d_in[8];
    const float* d3_b   = (const float*)d_in[9];
    const float* d5_w   = (const float*)d_in[10];
    const float* d5_b   = (const float*)d_in[11];
    const float* proj_w = (const float*)d_in[12];
    float* out = (float*)d_out;

    // 1) t = pos 1x1 conv:  (384,128) @ x
    gemm_f2<384, 128, 0><<<dim3(HW / 128, 3, Bc), 256>>>(pos_w, x, pos_b, nullptr);

    // 2) qkv = concat(qd3(t), qd5(t))
    dualconv<0><<<dim3(16, 192, Bc), 256>>>(nullptr, qd3_w, qd3_b, qd5_w, qd5_b);

    // 3) gram partials + fused ssq, 8 n-chunks
    gram_k<<<dim3(64, 8), 256>>>();

    // 4) normalize + temperature + softmax -> attn
    softmax_k<<<64, 256>>>(temp);

    // 5) y[0:128] = attn @ v
    av_k<<<dim3(HW / 1024, 64), 256>>>();

    // 6) y[128:256] = concat(d3(x), d5(x))
    dualconv<1><<<dim3(16, 64, Bc), 256>>>(x, d3_w, d3_b, d5_w, d5_b);

    // 7) result = proj 1x1 conv: (128,256) @ y
    gemm_f2<128, 256, 1><<<dim3(HW / 128, 1, Bc), 256>>>(proj_w, nullptr, nullptr, out);
}

// round 12
// speedup vs baseline: 1.3430x; 1.1860x over previous
#include <cuda_runtime.h>
#include <cuda_bf16.h>
#include <math.h>
#include <cstdint>

// Problem constants
#define Bc   8
#define Cc   128
#define Hd   128
#define Wd   128
#define HW   16384          // Hd*Wd
#define NH   8

typedef unsigned long long ull;

__device__ __forceinline__ ull fma2(ull a, ull b, ull c) {
    ull d;
    asm("fma.rn.f32x2 %0, %1, %2, %3;" : "=l"(d) : "l"(a), "l"(b), "l"(c));
    return d;
}

__device__ __forceinline__ uint32_t smem_u32(const void* p) {
    uint32_t a;
    asm("{ .reg .u64 t; cvta.to.shared.u64 t, %1; cvt.u32.u64 %0, t; }" : "=r"(a) : "l"(p));
    return a;
}

// ---------------- mma.sync helpers (base sm_103-compatible) -----------------
__device__ __forceinline__ void mma_bf16(float* d, const uint32_t* a, const uint32_t* b) {
    asm volatile(
        "mma.sync.aligned.m16n8k16.row.col.f32.bf16.bf16.f32 "
        "{%0,%1,%2,%3}, {%4,%5,%6,%7}, {%8,%9}, {%0,%1,%2,%3};"
        : "+f"(d[0]), "+f"(d[1]), "+f"(d[2]), "+f"(d[3])
        : "r"(a[0]), "r"(a[1]), "r"(a[2]), "r"(a[3]), "r"(b[0]), "r"(b[1]));
}
__device__ __forceinline__ void ldsm_x4(uint32_t* r, uint32_t addr) {
    asm volatile("ldmatrix.sync.aligned.m8n8.x4.shared.b16 {%0,%1,%2,%3}, [%4];"
        : "=r"(r[0]), "=r"(r[1]), "=r"(r[2]), "=r"(r[3]) : "r"(addr));
}
__device__ __forceinline__ void ldsm_x2_trans(uint32_t* r, uint32_t addr) {
    asm volatile("ldmatrix.sync.aligned.m8n8.x2.trans.shared.b16 {%0,%1}, [%2];"
        : "=r"(r[0]), "=r"(r[1]) : "r"(addr));
}

__device__ __forceinline__ uint32_t pack_hi2(float v0, float v1, float* r0, float* r1) {
    __nv_bfloat16 h0 = __float2bfloat16(v0);
    __nv_bfloat16 h1 = __float2bfloat16(v1);
    *r0 = v0 - __bfloat162float(h0);
    *r1 = v1 - __bfloat162float(h1);
    return (uint32_t)__bfloat16_as_ushort(h0) | ((uint32_t)__bfloat16_as_ushort(h1) << 16);
}
__device__ __forceinline__ uint32_t pack_bf2(float v0, float v1) {
    __nv_bfloat16 h0 = __float2bfloat16(v0);
    __nv_bfloat16 h1 = __float2bfloat16(v1);
    return (uint32_t)__bfloat16_as_ushort(h0) | ((uint32_t)__bfloat16_as_ushort(h1) << 16);
}

// ---------------- scratch (static device memory; no allocations) ------------
__device__ float g_t  [(size_t)Bc * 384 * HW];   // pos-conv output (B,384,HW)
__device__ float g_qkv[(size_t)Bc * 384 * HW];   // concat(qd3,qd5)  (B,384,HW)
__device__ float g_y  [(size_t)Bc * 256 * HW];   // concat(out,d3,d5)(B,256,HW)
__device__ float g_ssqp[8 * 64 * 32];            // [chunk][bh][16 q + 16 k] ssq partials
__device__ float g_gram[8 * 64 * 256];           // 8 n-chunk partials of 16x16 grams
__device__ float g_attn[64 * 256];               // softmaxed attention (bh, d, e)

// =============================================================================
// 1x1 conv as HMMA (mma.sync bf16) 3-term split-precision GEMM.
// C[b,m,n] = sum_k W[m,k] * X[b,k,n] (+ bias[m])
// CTA: 256 thr, tile 128m x 128n x 32k. Warps 2m x 4n; warp tile 64x32.
// MODE 0: X = x input,  C = g_t,  M=384, K=128, bias
// MODE 1: X = g_y,      C = out,  M=128, K=256, no bias
// =============================================================================
template<int M, int K, int MODE>
__global__ void __launch_bounds__(256, 1) gemm_mma(const float* __restrict__ W,
                                                   const float* __restrict__ Xext,
                                                   const float* __restrict__ bias,
                                                   float* __restrict__ Cext)
{
    // smem: row pads chosen so ldmatrix row sets hit distinct banks
    __shared__ __nv_bfloat16 Whi[128][40], Wlo[128][40];   // 32 k + 8 pad  (80B stride)
    __shared__ __nv_bfloat16 Xhi[32][136], Xlo[32][136];   // 128 n + 8 pad (272B stride)
    __shared__ float sbias[128];

    const float* X = (MODE == 0) ? Xext : g_y;
    float*       C = (MODE == 0) ? g_t  : Cext;

    const int b  = blockIdx.z;
    const int m0 = blockIdx.y * 128;
    const int n0 = blockIdx.x * 128;

    const int t    = threadIdx.x;
    const int wid  = t >> 5, lane = t & 31;
    const int wm   = wid >> 2, wn = wid & 3;    // 2 x 4 warp grid

    if (MODE == 0 && t < 128) sbias[t] = bias[m0 + t];

    float acc[4][4][4];
#pragma unroll
    for (int i = 0; i < 4; i++)
#pragma unroll
        for (int j = 0; j < 4; j++)
#pragma unroll
            for (int f = 0; f < 4; f++) acc[i][j][f] = 0.f;

    // global load mapping
    const float* Wr = W + (size_t)(m0 + (t >> 1)) * K + (t & 1) * 16;  // row t>>1, 16 k
    const float* Xb = X + (size_t)b * K * HW + n0;

    const uint32_t whi_b = smem_u32(&Whi[0][0]);
    const uint32_t wlo_b = smem_u32(&Wlo[0][0]);
    const uint32_t xhi_b = smem_u32(&Xhi[0][0]);
    const uint32_t xlo_b = smem_u32(&Xlo[0][0]);

    for (int k0 = 0; k0 < K; k0 += 32) {
        // ---- W chunk: 128 rows x 32 k. Thread: row t>>1, k half (t&1)*16 ----
        {
            const float* p = Wr + k0;
            float4 f[4];
#pragma unroll
            for (int q = 0; q < 4; q++) f[q] = *(const float4*)(p + q * 4);
            uint32_t hi[8], lo[8];
#pragma unroll
            for (int q = 0; q < 4; q++) {
                float l0, l1, l2, l3;
                hi[2*q]   = pack_hi2(f[q].x, f[q].y, &l0, &l1);
                hi[2*q+1] = pack_hi2(f[q].z, f[q].w, &l2, &l3);
                lo[2*q]   = pack_bf2(l0, l1);
                lo[2*q+1] = pack_bf2(l2, l3);
            }
            __nv_bfloat16* dh = &Whi[t >> 1][(t & 1) * 16];
            __nv_bfloat16* dl = &Wlo[t >> 1][(t & 1) * 16];
            ((uint4*)dh)[0] = make_uint4(hi[0], hi[1], hi[2], hi[3]);
            ((uint4*)dh)[1] = make_uint4(hi[4], hi[5], hi[6], hi[7]);
            ((uint4*)dl)[0] = make_uint4(lo[0], lo[1], lo[2], lo[3]);
            ((uint4*)dl)[1] = make_uint4(lo[4], lo[5], lo[6], lo[7]);
        }
        // ---- X chunk: 32 k-rows x 128 n. Thread: k row t>>3, n (t&7)*16 ----
        {
            const float* p = Xb + (size_t)(k0 + (t >> 3)) * HW + (t & 7) * 16;
            float4 f[4];
#pragma unroll
            for (int q = 0; q < 4; q++) f[q] = *(const float4*)(p + q * 4);
            uint32_t hi[8], lo[8];
#pragma unroll
            for (int q = 0; q < 4; q++) {
                float l0, l1, l2, l3;
                hi[2*q]   = pack_hi2(f[q].x, f[q].y, &l0, &l1);
                hi[2*q+1] = pack_hi2(f[q].z, f[q].w, &l2, &l3);
                lo[2*q]   = pack_bf2(l0, l1);
                lo[2*q+1] = pack_bf2(l2, l3);
            }
            __nv_bfloat16* dh = &Xhi[t >> 3][(t & 7) * 16];
            __nv_bfloat16* dl = &Xlo[t >> 3][(t & 7) * 16];
            ((uint4*)dh)[0] = make_uint4(hi[0], hi[1], hi[2], hi[3]);
            ((uint4*)dh)[1] = make_uint4(hi[4], hi[5], hi[6], hi[7]);
            ((uint4*)dl)[0] = make_uint4(lo[0], lo[1], lo[2], lo[3]);
            ((uint4*)dl)[1] = make_uint4(lo[4], lo[5], lo[6], lo[7]);
        }
        __syncthreads();

#pragma unroll
        for (int ks = 0; ks < 2; ks++) {
            // A fragments: 4 mtiles x (hi,lo)
            uint32_t ahi[4][4], alo[4][4];
            const uint32_t arow = (uint32_t)(wm * 64 + (lane & 15));
            const uint32_t acol = (uint32_t)(ks * 16 + (lane >> 4) * 8);
#pragma unroll
            for (int mt = 0; mt < 4; mt++) {
                uint32_t off = ((arow + mt * 16) * 40u + acol) * 2u;
                ldsm_x4(ahi[mt], whi_b + off);
                ldsm_x4(alo[mt], wlo_b + off);
            }
            const uint32_t brow = (uint32_t)(ks * 16 + (lane & 15));
#pragma unroll
            for (int nt = 0; nt < 4; nt++) {
                uint32_t bhi[2], blo[2];
                uint32_t off = (brow * 136u + (uint32_t)(wn * 32 + nt * 8)) * 2u;
                ldsm_x2_trans(bhi, xhi_b + off);
                ldsm_x2_trans(blo, xlo_b + off);
#pragma unroll
                for (int mt = 0; mt < 4; mt++) {
                    mma_bf16(acc[mt][nt], ahi[mt], bhi);
                    mma_bf16(acc[mt][nt], ahi[mt], blo);
                    mma_bf16(acc[mt][nt], alo[mt], bhi);
                }
            }
        }
        __syncthreads();
    }

    // ---- epilogue: fragment direct store ----
#pragma unroll
    for (int mt = 0; mt < 4; mt++) {
        const int rloc = wm * 64 + mt * 16 + (lane >> 2);
        const int r  = m0 + rloc;
        const float bb0 = (MODE == 0) ? sbias[rloc]     : 0.f;
        const float bb1 = (MODE == 0) ? sbias[rloc + 8] : 0.f;
        float* C0 = C + ((size_t)b * M + r)     * HW + n0 + wn * 32 + (lane & 3) * 2;
        float* C1 = C + ((size_t)b * M + r + 8) * HW + n0 + wn * 32 + (lane & 3) * 2;
#pragma unroll
        for (int nt = 0; nt < 4; nt++) {
            *(float2*)(C0 + nt * 8) = make_float2(acc[mt][nt][0] + bb0, acc[mt][nt][1] + bb0);
            *(float2*)(C1 + nt * 8) = make_float2(acc[mt][nt][2] + bb1, acc[mt][nt][3] + bb1);
        }
    }
}

// ---------------- dual grouped conv (3x3 pad1 + 5x5 pad2, 2 in-ch/group) ----
template<int MODE>
__global__ void __launch_bounds__(256) dualconv(const float* __restrict__ xin,
                                                const float* __restrict__ w3,
                                                const float* __restrict__ b3,
                                                const float* __restrict__ w5,
                                                const float* __restrict__ b5)
{
    constexpr int Cin  = MODE ? 128 : 384;
    constexpr int TotC = MODE ? 256 : 384;
    constexpr int C3B  = MODE ? 128 : 0;
    constexpr int C5B  = 192;

    const float* in  = MODE ? xin : g_t;
    float*       out = MODE ? g_y : g_qkv;

    const int g    = blockIdx.y;
    const int b    = blockIdx.z;
    const int tile = blockIdx.x;          // 0..15 (4x4 tiles of 32x32)
    const int X0 = (tile & 3) * 32;
    const int Y0 = (tile >> 2) * 32;

    __shared__ float sm[2 * 36 * 36];
    __shared__ float sw3[18], sw5[50], sb[2];

    const int t = threadIdx.x;
    if (t < 18)       sw3[t]      = w3[g * 18 + t];
    else if (t < 68)  sw5[t - 18] = w5[g * 50 + (t - 18)];
    else if (t == 68) sb[0] = b3[g];
    else if (t == 69) sb[1] = b5[g];

    const float* inb = in + ((size_t)b * Cin + 2 * g) * HW;
    for (int i = t; i < 2 * 36 * 36; i += 256) {
        int ch = i / 1296;
        int r  = i - ch * 1296;
        int y  = r / 36;
        int x  = r - y * 36;
        int gy = Y0 - 2 + y, gx = X0 - 2 + x;
        float v = 0.f;
        if ((unsigned)gy < (unsigned)Hd && (unsigned)gx < (unsigned)Wd)
            v = inb[(size_t)ch * HW + gy * Wd + gx];
        sm[i] = v;
    }
    __syncthreads();

    const int ty  = t >> 3;          // 0..31 output row
    const int txb = (t & 7) * 4;     // 4 consecutive output cols

    float a3[4], a5[4];
#pragma unroll
    for (int j = 0; j < 4; j++) { a3[j] = sb[0]; a5[j] = sb[1]; }

#pragma unroll
    for (int ch = 0; ch < 2; ch++) {
        const float* smc = sm + ch * 1296;
#pragma unroll
        for (int ky = 0; ky < 5; ky++) {
            float row[8];
            const float* rp = smc + (ty + ky) * 36 + txb;
#pragma unroll
            for (int x = 0; x < 8; x++) row[x] = rp[x];
#pragma unroll
            for (int kx = 0; kx < 5; kx++) {
                const float w = sw5[ch * 25 + ky * 5 + kx];
#pragma unroll
                for (int j = 0; j < 4; j++) a5[j] += w * row[kx + j];
            }
            if (ky >= 1 && ky <= 3) {
#pragma unroll
                for (int kx = 0; kx < 3; kx++) {
                    const float w = sw3[ch * 9 + (ky - 1) * 3 + kx];
#pragma unroll
                    for (int j = 0; j < 4; j++) a3[j] += w * row[kx + 1 + j];
                }
            }
        }
    }

    const size_t p = (size_t)(Y0 + ty) * Wd + X0 + txb;
    *(float4*)(out + ((size_t)b * TotC + C3B + g) * HW + p) =
        make_float4(a3[0], a3[1], a3[2], a3[3]);
    *(float4*)(out + ((size_t)b * TotC + C5B + g) * HW + p) =
        make_float4(a5[0], a5[1], a5[2], a5[3]);
}

// ---------------- gram + fused ssq: G[bh][d][e] partials over 8 n-chunks ----
__global__ void __launch_bounds__(256) gram_k()
{
    const int bh    = blockIdx.x;     // 0..63
    const int b     = bh >> 3, h = bh & 7;
    const int chunk = blockIdx.y;     // 0..7  (2048 n each)

    const float* qp = g_qkv + ((size_t)b * 384 +       h * 16) * HW;
    const float* kp = g_qkv + ((size_t)b * 384 + 128 + h * 16) * HW;

    __shared__ float qs[16][132];
    __shared__ float ks[16][132];

    const int t = threadIdx.x;
    const int d = t >> 4, e = t & 15;

    const int cl0 = t >> 5;           // 0..7
    const int nl0 = (t & 31) * 4;

    ull acc_a = 0, acc_b = 0;
    ull sq_q0 = 0, sq_q1 = 0, sq_k0 = 0, sq_k1 = 0;

    const int nbeg = chunk * 2048;
    for (int n0 = nbeg; n0 < nbeg + 2048; n0 += 128) {
        float4 q0 = *(const float4*)(qp + (size_t)cl0 * HW + n0 + nl0);
        float4 q1 = *(const float4*)(qp + (size_t)(cl0 + 8) * HW + n0 + nl0);
        float4 k0 = *(const float4*)(kp + (size_t)cl0 * HW + n0 + nl0);
        float4 k1 = *(const float4*)(kp + (size_t)(cl0 + 8) * HW + n0 + nl0);
        ull* q0p = (ull*)&q0; ull* q1p = (ull*)&q1;
        ull* k0p = (ull*)&k0; ull* k1p = (ull*)&k1;
        sq_q0 = fma2(q0p[0], q0p[0], sq_q0); sq_q0 = fma2(q0p[1], q0p[1], sq_q0);
        sq_q1 = fma2(q1p[0], q1p[0], sq_q1); sq_q1 = fma2(q1p[1], q1p[1], sq_q1);
        sq_k0 = fma2(k0p[0], k0p[0], sq_k0); sq_k0 = fma2(k0p[1], k0p[1], sq_k0);
        sq_k1 = fma2(k1p[0], k1p[0], sq_k1); sq_k1 = fma2(k1p[1], k1p[1], sq_k1);

        *(float4*)&qs[cl0    ][nl0] = q0;
        *(float4*)&qs[cl0 + 8][nl0] = q1;
        *(float4*)&ks[cl0    ][nl0] = k0;
        *(float4*)&ks[cl0 + 8][nl0] = k1;
        __syncthreads();

#pragma unroll 8
        for (int n = 0; n < 128; n += 4) {
            ull q01 = *(const ull*)&qs[d][n];
            ull q23 = *(const ull*)&qs[d][n + 2];
            ull k01 = *(const ull*)&ks[e][n];
            ull k23 = *(const ull*)&ks[e][n + 2];
            acc_a = fma2(q01, k01, acc_a);
            acc_b = fma2(q23, k23, acc_b);
        }
        __syncthreads();
    }

    {
        float2 pa = *(float2*)&acc_a, pb = *(float2*)&acc_b;
        g_gram[((size_t)chunk * 64 + bh) * 256 + t] = pa.x + pa.y + pb.x + pb.y;
    }

    float2 a;
    a = *(float2*)&sq_q0; float vq0 = a.x + a.y;
    a = *(float2*)&sq_q1; float vq1 = a.x + a.y;
    a = *(float2*)&sq_k0; float vk0 = a.x + a.y;
    a = *(float2*)&sq_k1; float vk1 = a.x + a.y;
#pragma unroll
    for (int o = 16; o > 0; o >>= 1) {
        vq0 += __shfl_xor_sync(0xffffffffu, vq0, o);
        vq1 += __shfl_xor_sync(0xffffffffu, vq1, o);
        vk0 += __shfl_xor_sync(0xffffffffu, vk0, o);
        vk1 += __shfl_xor_sync(0xffffffffu, vk1, o);
    }
    if ((t & 31) == 0) {
        float* dst = g_ssqp + ((size_t)chunk * 64 + bh) * 32;
        dst[cl0]          = vq0;
        dst[cl0 + 8]      = vq1;
        dst[16 + cl0]     = vk0;
        dst[16 + cl0 + 8] = vk1;
    }
}

// ---------------- softmax over e with l2-normalization + temperature --------
__global__ void __launch_bounds__(256) softmax_k(const float* __restrict__ temp)
{
    const int bh = blockIdx.x;
    const int h  = bh & 7;
    const int t  = threadIdx.x;
    const int d  = t >> 4, e = t & 15;

    float gsum = 0.f, sq = 0.f, sk = 0.f;
#pragma unroll
    for (int c = 0; c < 8; c++) {
        gsum += g_gram[((size_t)c * 64 + bh) * 256 + t];
        sq   += g_ssqp[((size_t)c * 64 + bh) * 32 + d];
        sk   += g_ssqp[((size_t)c * 64 + bh) * 32 + 16 + e];
    }

    const float nq = fmaxf(sqrtf(sq), 1e-12f);
    const float nk = fmaxf(sqrtf(sk), 1e-12f);
    float logit = gsum / (nq * nk) * temp[h];

    float m = logit;
#pragma unroll
    for (int o = 8; o > 0; o >>= 1)
        m = fmaxf(m, __shfl_xor_sync(0xffffffffu, m, o));
    float ex = expf(logit - m);
    float s = ex;
#pragma unroll
    for (int o = 8; o > 0; o >>= 1)
        s += __shfl_xor_sync(0xffffffffu, s, o);

    g_attn[bh * 256 + t] = ex / s;
}

// ---------------- out = attn @ v  -> y channels 0..127 (4n per thread) ------
__global__ void __launch_bounds__(256) av_k()
{
    const int bh = blockIdx.y;
    const int b  = bh >> 3, h = bh & 7;
    const int n  = blockIdx.x * 1024 + threadIdx.x * 4;

    __shared__ float As[256];
    As[threadIdx.x] = g_attn[bh * 256 + threadIdx.x];
    __syncthreads();

    const float* vp = g_qkv + ((size_t)b * 384 + 256 + h * 16) * HW + n;
    float acc[16][4];
#pragma unroll
    for (int dd = 0; dd < 16; dd++)
#pragma unroll
        for (int c = 0; c < 4; c++) acc[dd][c] = 0.f;

#pragma unroll
    for (int e = 0; e < 16; e++) {
        const float4 v4 = *(const float4*)(vp + (size_t)e * HW);
#pragma unroll
        for (int dd = 0; dd < 16; dd++) {
            const float w = As[dd * 16 + e];
            acc[dd][0] += w * v4.x;
            acc[dd][1] += w * v4.y;
            acc[dd][2] += w * v4.z;
            acc[dd][3] += w * v4.w;
        }
    }
    float* yp = g_y + ((size_t)b * 256 + h * 16) * HW + n;
#pragma unroll
    for (int dd = 0; dd < 16; dd++)
        *(float4*)(yp + (size_t)dd * HW) =
            make_float4(acc[dd][0], acc[dd][1], acc[dd][2], acc[dd][3]);
}

// ---------------- launcher ---------------------------------------------------
extern "C" void kernel_launch(void* const* d_in, const int* in_sizes, int n_in,
                              void* d_out, int out_size)
{
    const float* x      = (const float*)d_in[0];
    const float* pos_w  = (const float*)d_in[1];
    const float* pos_b  = (const float*)d_in[2];
    const float* qd3_w  = (const float*)d_in[3];
    const float* qd3_b  = (const float*)d_in[4];
    const float* qd5_w  = (const float*)d_in[5];
    const float* qd5_b  = (const float*)d_in[6];
    const float* temp   = (const float*)d_in[7];
    const float* d3_w   = (const float*)d_in[8];
    const float* d3_b   = (const float*)d_in[9];
    const float* d5_w   = (const float*)d_in[10];
    const float* d5_b   = (const float*)d_in[11];
    const float* proj_w = (const float*)d_in[12];
    float* out = (float*)d_out;

    // 1) t = pos 1x1 conv:  (384,128) @ x
    gemm_mma<384, 128, 0><<<dim3(HW / 128, 3, Bc), 256>>>(pos_w, x, pos_b, nullptr);

    // 2) qkv = concat(qd3(t), qd5(t))
    dualconv<0><<<dim3(16, 192, Bc), 256>>>(nullptr, qd3_w, qd3_b, qd5_w, qd5_b);

    // 3) gram partials + fused ssq, 8 n-chunks
    gram_k<<<dim3(64, 8), 256>>>();

    // 4) normalize + temperature + softmax -> attn
    softmax_k<<<64, 256>>>(temp);

    // 5) y[0:128] = attn @ v
    av_k<<<dim3(HW / 1024, 64), 256>>>();

    // 6) y[128:256] = concat(d3(x), d5(x))
    dualconv<1><<<dim3(16, 64, Bc), 256>>>(x, d3_w, d3_b, d5_w, d5_b);

    // 7) result = proj 1x1 conv: (128,256) @ y
    gemm_mma<128, 256, 1><<<dim3(HW / 128, 1, Bc), 256>>>(proj_w, nullptr, nullptr, out);
}

// round 16
// speedup vs baseline: 1.4770x; 1.0998x over previous
#include <cuda_runtime.h>
#include <cuda_bf16.h>
#include <math.h>
#include <cstdint>

// Problem constants
#define Bc   8
#define Cc   128
#define Hd   128
#define Wd   128
#define HW   16384          // Hd*Wd
#define NH   8

typedef unsigned long long ull;

__device__ __forceinline__ ull fma2(ull a, ull b, ull c) {
    ull d;
    asm("fma.rn.f32x2 %0, %1, %2, %3;" : "=l"(d) : "l"(a), "l"(b), "l"(c));
    return d;
}

__device__ __forceinline__ uint32_t smem_u32(const void* p) {
    uint32_t a;
    asm("{ .reg .u64 t; cvta.to.shared.u64 t, %1; cvt.u32.u64 %0, t; }" : "=r"(a) : "l"(p));
    return a;
}

// ---------------- mma.sync helpers (base sm_103-compatible) -----------------
__device__ __forceinline__ void mma_bf16(float* d, const uint32_t* a, const uint32_t* b) {
    asm volatile(
        "mma.sync.aligned.m16n8k16.row.col.f32.bf16.bf16.f32 "
        "{%0,%1,%2,%3}, {%4,%5,%6,%7}, {%8,%9}, {%0,%1,%2,%3};"
        : "+f"(d[0]), "+f"(d[1]), "+f"(d[2]), "+f"(d[3])
        : "r"(a[0]), "r"(a[1]), "r"(a[2]), "r"(a[3]), "r"(b[0]), "r"(b[1]));
}
__device__ __forceinline__ void ldsm_x4(uint32_t* r, uint32_t addr) {
    asm volatile("ldmatrix.sync.aligned.m8n8.x4.shared.b16 {%0,%1,%2,%3}, [%4];"
        : "=r"(r[0]), "=r"(r[1]), "=r"(r[2]), "=r"(r[3]) : "r"(addr));
}
__device__ __forceinline__ void ldsm_x2_trans(uint32_t* r, uint32_t addr) {
    asm volatile("ldmatrix.sync.aligned.m8n8.x2.trans.shared.b16 {%0,%1}, [%2];"
        : "=r"(r[0]), "=r"(r[1]) : "r"(addr));
}

// Cheap 2-element fp32 -> (bf16hi trunc, bf16lo rn) split.
// hi pair: one PRMT (high halves of v0,v1). hi-as-float: AND mask (exact).
// lo = v - hi (exact); lo pair: one cvt.rn.bf16x2.f32.
__device__ __forceinline__ void cvt_split2(float v0, float v1,
                                           uint32_t* hi, uint32_t* lo) {
    uint32_t u0 = __float_as_uint(v0), u1 = __float_as_uint(v1);
    uint32_t hp;
    asm("prmt.b32 %0, %1, %2, 0x7632;" : "=r"(hp) : "r"(u0), "r"(u1));
    float h0 = __uint_as_float(u0 & 0xFFFF0000u);
    float h1 = __uint_as_float(u1 & 0xFFFF0000u);
    float l0 = v0 - h0, l1 = v1 - h1;
    uint32_t lp;
    asm("cvt.rn.bf16x2.f32 %0, %1, %2;" : "=r"(lp) : "f"(l1), "f"(l0));
    *hi = hp; *lo = lp;
}
__device__ __forceinline__ void cvt_split_f4(float4 f, uint32_t* hi2, uint32_t* lo2) {
    cvt_split2(f.x, f.y, &hi2[0], &lo2[0]);
    cvt_split2(f.z, f.w, &hi2[1], &lo2[1]);
}

// ---------------- scratch (static device memory; no allocations) ------------
__device__ float g_t  [(size_t)Bc * 384 * HW];   // pos-conv output (B,384,HW)
__device__ float g_qkv[(size_t)Bc * 384 * HW];   // concat(qd3,qd5)  (B,384,HW)
__device__ float g_y  [(size_t)Bc * 256 * HW];   // concat(out,d3,d5)(B,256,HW)
__device__ float g_ssqp[8 * 64 * 32];            // [chunk][bh][16 q + 16 k] ssq partials
__device__ float g_gram[8 * 64 * 256];           // 8 n-chunk partials of 16x16 grams
__device__ float g_attn[64 * 256];               // softmaxed attention (bh, d, e)

// =============================================================================
// 1x1 conv as HMMA (mma.sync bf16) 3-term split-precision GEMM.
// C[b,m,n] = sum_k W[m,k] * X[b,k,n] (+ bias[m])
// CTA: 256 thr, tile 128m x 128n x 32k. Warps 2m x 4n; warp tile 64x32.
// X (streaming, DRAM) is register-prefetched one chunk ahead so its LDGs
// overlap the MMA phase; W (L2-resident) converts inline.
// MODE 0: X = x input,  C = g_t,  M=384, K=128, bias
// MODE 1: X = g_y,      C = out,  M=128, K=256, no bias
// =============================================================================
template<int M, int K, int MODE>
__global__ void __launch_bounds__(256, 1) gemm_mma(const float* __restrict__ W,
                                                   const float* __restrict__ Xext,
                                                   const float* __restrict__ bias,
                                                   float* __restrict__ Cext)
{
    // smem: row pads chosen so ldmatrix row sets hit distinct banks
    __shared__ __nv_bfloat16 Whi[128][40], Wlo[128][40];   // 32 k + 8 pad  (80B stride)
    __shared__ __nv_bfloat16 Xhi[32][136], Xlo[32][136];   // 128 n + 8 pad (272B stride)
    __shared__ float sbias[128];

    const float* X = (MODE == 0) ? Xext : g_y;
    float*       C = (MODE == 0) ? g_t  : Cext;

    const int b  = blockIdx.z;
    const int m0 = blockIdx.y * 128;
    const int n0 = blockIdx.x * 128;

    const int t    = threadIdx.x;
    const int wid  = t >> 5, lane = t & 31;
    const int wm   = wid >> 2, wn = wid & 3;    // 2 x 4 warp grid

    if (MODE == 0 && t < 128) sbias[t] = bias[m0 + t];

    float acc[4][4][4];
#pragma unroll
    for (int i = 0; i < 4; i++)
#pragma unroll
        for (int j = 0; j < 4; j++)
#pragma unroll
            for (int f = 0; f < 4; f++) acc[i][j][f] = 0.f;

    // global load mapping
    const float* Wr = W + (size_t)(m0 + (t >> 1)) * K + (t & 1) * 16;  // row t>>1, 16 k
    const float* Xr = X + (size_t)b * K * HW + n0 + (t & 7) * 16;      // + k-row via t>>3

    const uint32_t whi_b = smem_u32(&Whi[0][0]);
    const uint32_t wlo_b = smem_u32(&Wlo[0][0]);
    const uint32_t xhi_b = smem_u32(&Xhi[0][0]);
    const uint32_t xlo_b = smem_u32(&Xlo[0][0]);

    // prefetch X chunk 0 into registers
    float4 fX[4];
#pragma unroll
    for (int q = 0; q < 4; q++)
        fX[q] = *(const float4*)(Xr + (size_t)(t >> 3) * HW + q * 4);

    for (int k0 = 0; k0 < K; k0 += 32) {
        // ---- W chunk (L2-hot): load + convert + store ----
        {
            const float* p = Wr + k0;
            uint32_t hi[8], lo[8];
#pragma unroll
            for (int q = 0; q < 4; q++) {
                float4 f = *(const float4*)(p + q * 4);
                cvt_split_f4(f, &hi[2 * q], &lo[2 * q]);
            }
            __nv_bfloat16* dh = &Whi[t >> 1][(t & 1) * 16];
            __nv_bfloat16* dl = &Wlo[t >> 1][(t & 1) * 16];
            ((uint4*)dh)[0] = make_uint4(hi[0], hi[1], hi[2], hi[3]);
            ((uint4*)dh)[1] = make_uint4(hi[4], hi[5], hi[6], hi[7]);
            ((uint4*)dl)[0] = make_uint4(lo[0], lo[1], lo[2], lo[3]);
            ((uint4*)dl)[1] = make_uint4(lo[4], lo[5], lo[6], lo[7]);
        }
        // ---- X chunk: convert prefetched regs -> smem ----
        {
            uint32_t hi[8], lo[8];
#pragma unroll
            for (int q = 0; q < 4; q++)
                cvt_split_f4(fX[q], &hi[2 * q], &lo[2 * q]);
            __nv_bfloat16* dh = &Xhi[t >> 3][(t & 7) * 16];
            __nv_bfloat16* dl = &Xlo[t >> 3][(t & 7) * 16];
            ((uint4*)dh)[0] = make_uint4(hi[0], hi[1], hi[2], hi[3]);
            ((uint4*)dh)[1] = make_uint4(hi[4], hi[5], hi[6], hi[7]);
            ((uint4*)dl)[0] = make_uint4(lo[0], lo[1], lo[2], lo[3]);
            ((uint4*)dl)[1] = make_uint4(lo[4], lo[5], lo[6], lo[7]);
        }
        __syncthreads();

        // ---- prefetch next X chunk (LDGs overlap the MMA phase below) ----
        if (k0 + 32 < K) {
#pragma unroll
            for (int q = 0; q < 4; q++)
                fX[q] = *(const float4*)(Xr + (size_t)(k0 + 32 + (t >> 3)) * HW + q * 4);
        }

#pragma unroll
        for (int ks = 0; ks < 2; ks++) {
            // A fragments: 4 mtiles x (hi,lo)
            uint32_t ahi[4][4], alo[4][4];
            const uint32_t arow = (uint32_t)(wm * 64 + (lane & 15));
            const uint32_t acol = (uint32_t)(ks * 16 + (lane >> 4) * 8);
#pragma unroll
            for (int mt = 0; mt < 4; mt++) {
                uint32_t off = ((arow + mt * 16) * 40u + acol) * 2u;
                ldsm_x4(ahi[mt], whi_b + off);
                ldsm_x4(alo[mt], wlo_b + off);
            }
            const uint32_t brow = (uint32_t)(ks * 16 + (lane & 15));
#pragma unroll
            for (int nt = 0; nt < 4; nt++) {
                uint32_t bhi[2], blo[2];
                uint32_t off = (brow * 136u + (uint32_t)(wn * 32 + nt * 8)) * 2u;
                ldsm_x2_trans(bhi, xhi_b + off);
                ldsm_x2_trans(blo, xlo_b + off);
#pragma unroll
                for (int mt = 0; mt < 4; mt++) {
                    mma_bf16(acc[mt][nt], ahi[mt], bhi);
                    mma_bf16(acc[mt][nt], ahi[mt], blo);
                    mma_bf16(acc[mt][nt], alo[mt], bhi);
                }
            }
        }
        __syncthreads();
    }

    // ---- epilogue: fragment direct store ----
#pragma unroll
    for (int mt = 0; mt < 4; mt++) {
        const int rloc = wm * 64 + mt * 16 + (lane >> 2);
        const int r  = m0 + rloc;
        const float bb0 = (MODE == 0) ? sbias[rloc]     : 0.f;
        const float bb1 = (MODE == 0) ? sbias[rloc + 8] : 0.f;
        float* C0 = C + ((size_t)b * M + r)     * HW + n0 + wn * 32 + (lane & 3) * 2;
        float* C1 = C + ((size_t)b * M + r + 8) * HW + n0 + wn * 32 + (lane & 3) * 2;
#pragma unroll
        for (int nt = 0; nt < 4; nt++) {
            *(float2*)(C0 + nt * 8) = make_float2(acc[mt][nt][0] + bb0, acc[mt][nt][1] + bb0);
            *(float2*)(C1 + nt * 8) = make_float2(acc[mt][nt][2] + bb1, acc[mt][nt][3] + bb1);
        }
    }
}

// ---------------- dual grouped conv (3x3 pad1 + 5x5 pad2, 2 in-ch/group) ----
template<int MODE>
__global__ void __launch_bounds__(256) dualconv(const float* __restrict__ xin,
                                                const float* __restrict__ w3,
                                                const float* __restrict__ b3,
                                                const float* __restrict__ w5,
                                                const float* __restrict__ b5)
{
    constexpr int Cin  = MODE ? 128 : 384;
    constexpr int TotC = MODE ? 256 : 384;
    constexpr int C3B  = MODE ? 128 : 0;
    constexpr int C5B  = 192;

    const float* in  = MODE ? xin : g_t;
    float*       out = MODE ? g_y : g_qkv;

    const int g    = blockIdx.y;
    const int b    = blockIdx.z;
    const int tile = blockIdx.x;          // 0..15 (4x4 tiles of 32x32)
    const int X0 = (tile & 3) * 32;
    const int Y0 = (tile >> 2) * 32;

    __shared__ float sm[2 * 36 * 36];
    __shared__ float sw3[18], sw5[50], sb[2];

    const int t = threadIdx.x;
    if (t < 18)       sw3[t]      = w3[g * 18 + t];
    else if (t < 68)  sw5[t - 18] = w5[g * 50 + (t - 18)];
    else if (t == 68) sb[0] = b3[g];
    else if (t == 69) sb[1] = b5[g];

    const float* inb = in + ((size_t)b * Cin + 2 * g) * HW;
    for (int i = t; i < 2 * 36 * 36; i += 256) {
        int ch = i / 1296;
        int r  = i - ch * 1296;
        int y  = r / 36;
        int x  = r - y * 36;
        int gy = Y0 - 2 + y, gx = X0 - 2 + x;
        float v = 0.f;
        if ((unsigned)gy < (unsigned)Hd && (unsigned)gx < (unsigned)Wd)
            v = inb[(size_t)ch * HW + gy * Wd + gx];
        sm[i] = v;
    }
    __syncthreads();

    const int ty  = t >> 3;          // 0..31 output row
    const int txb = (t & 7) * 4;     // 4 consecutive output cols

    float a3[4], a5[4];
#pragma unroll
    for (int j = 0; j < 4; j++) { a3[j] = sb[0]; a5[j] = sb[1]; }

#pragma unroll
    for (int ch = 0; ch < 2; ch++) {
        const float* smc = sm + ch * 1296;
#pragma unroll
        for (int ky = 0; ky < 5; ky++) {
            float row[8];
            const float* rp = smc + (ty + ky) * 36 + txb;
#pragma unroll
            for (int x = 0; x < 8; x++) row[x] = rp[x];
#pragma unroll
            for (int kx = 0; kx < 5; kx++) {
                const float w = sw5[ch * 25 + ky * 5 + kx];
#pragma unroll
                for (int j = 0; j < 4; j++) a5[j] += w * row[kx + j];
            }
            if (ky >= 1 && ky <= 3) {
#pragma unroll
                for (int kx = 0; kx < 3; kx++) {
                    const float w = sw3[ch * 9 + (ky - 1) * 3 + kx];
#pragma unroll
                    for (int j = 0; j < 4; j++) a3[j] += w * row[kx + 1 + j];
                }
            }
        }
    }

    const size_t p = (size_t)(Y0 + ty) * Wd + X0 + txb;
    *(float4*)(out + ((size_t)b * TotC + C3B + g) * HW + p) =
        make_float4(a3[0], a3[1], a3[2], a3[3]);
    *(float4*)(out + ((size_t)b * TotC + C5B + g) * HW + p) =
        make_float4(a5[0], a5[1], a5[2], a5[3]);
}

// ---------------- gram + fused ssq: G[bh][d][e] partials over 8 n-chunks ----
__global__ void __launch_bounds__(256) gram_k()
{
    const int bh    = blockIdx.x;     // 0..63
    const int b     = bh >> 3, h = bh & 7;
    const int chunk = blockIdx.y;     // 0..7  (2048 n each)

    const float* qp = g_qkv + ((size_t)b * 384 +       h * 16) * HW;
    const float* kp = g_qkv + ((size_t)b * 384 + 128 + h * 16) * HW;

    __shared__ float qs[16][132];
    __shared__ float ks[16][132];

    const int t = threadIdx.x;
    const int d = t >> 4, e = t & 15;

    const int cl0 = t >> 5;           // 0..7
    const int nl0 = (t & 31) * 4;

    ull acc_a = 0, acc_b = 0;
    ull sq_q0 = 0, sq_q1 = 0, sq_k0 = 0, sq_k1 = 0;

    const int nbeg = chunk * 2048;
    for (int n0 = nbeg; n0 < nbeg + 2048; n0 += 128) {
        float4 q0 = *(const float4*)(qp + (size_t)cl0 * HW + n0 + nl0);
        float4 q1 = *(const float4*)(qp + (size_t)(cl0 + 8) * HW + n0 + nl0);
        float4 k0 = *(const float4*)(kp + (size_t)cl0 * HW + n0 + nl0);
        float4 k1 = *(const float4*)(kp + (size_t)(cl0 + 8) * HW + n0 + nl0);
        ull* q0p = (ull*)&q0; ull* q1p = (ull*)&q1;
        ull* k0p = (ull*)&k0; ull* k1p = (ull*)&k1;
        sq_q0 = fma2(q0p[0], q0p[0], sq_q0); sq_q0 = fma2(q0p[1], q0p[1], sq_q0);
        sq_q1 = fma2(q1p[0], q1p[0], sq_q1); sq_q1 = fma2(q1p[1], q1p[1], sq_q1);
        sq_k0 = fma2(k0p[0], k0p[0], sq_k0); sq_k0 = fma2(k0p[1], k0p[1], sq_k0);
        sq_k1 = fma2(k1p[0], k1p[0], sq_k1); sq_k1 = fma2(k1p[1], k1p[1], sq_k1);

        *(float4*)&qs[cl0    ][nl0] = q0;
        *(float4*)&qs[cl0 + 8][nl0] = q1;
        *(float4*)&ks[cl0    ][nl0] = k0;
        *(float4*)&ks[cl0 + 8][nl0] = k1;
        __syncthreads();

#pragma unroll 8
        for (int n = 0; n < 128; n += 4) {
            ull q01 = *(const ull*)&qs[d][n];
            ull q23 = *(const ull*)&qs[d][n + 2];
            ull k01 = *(const ull*)&ks[e][n];
            ull k23 = *(const ull*)&ks[e][n + 2];
            acc_a = fma2(q01, k01, acc_a);
            acc_b = fma2(q23, k23, acc_b);
        }
        __syncthreads();
    }

    {
        float2 pa = *(float2*)&acc_a, pb = *(float2*)&acc_b;
        g_gram[((size_t)chunk * 64 + bh) * 256 + t] = pa.x + pa.y + pb.x + pb.y;
    }

    float2 a;
    a = *(float2*)&sq_q0; float vq0 = a.x + a.y;
    a = *(float2*)&sq_q1; float vq1 = a.x + a.y;
    a = *(float2*)&sq_k0; float vk0 = a.x + a.y;
    a = *(float2*)&sq_k1; float vk1 = a.x + a.y;
#pragma unroll
    for (int o = 16; o > 0; o >>= 1) {
        vq0 += __shfl_xor_sync(0xffffffffu, vq0, o);
        vq1 += __shfl_xor_sync(0xffffffffu, vq1, o);
        vk0 += __shfl_xor_sync(0xffffffffu, vk0, o);
        vk1 += __shfl_xor_sync(0xffffffffu, vk1, o);
    }
    if ((t & 31) == 0) {
        float* dst = g_ssqp + ((size_t)chunk * 64 + bh) * 32;
        dst[cl0]          = vq0;
        dst[cl0 + 8]      = vq1;
        dst[16 + cl0]     = vk0;
        dst[16 + cl0 + 8] = vk1;
    }
}

// ---------------- softmax over e with l2-normalization + temperature --------
__global__ void __launch_bounds__(256) softmax_k(const float* __restrict__ temp)
{
    const int bh = blockIdx.x;
    const int h  = bh & 7;
    const int t  = threadIdx.x;
    const int d  = t >> 4, e = t & 15;

    float gsum = 0.f, sq = 0.f, sk = 0.f;
#pragma unroll
    for (int c = 0; c < 8; c++) {
        gsum += g_gram[((size_t)c * 64 + bh) * 256 + t];
        sq   += g_ssqp[((size_t)c * 64 + bh) * 32 + d];
        sk   += g_ssqp[((size_t)c * 64 + bh) * 32 + 16 + e];
    }

    const float nq = fmaxf(sqrtf(sq), 1e-12f);
    const float nk = fmaxf(sqrtf(sk), 1e-12f);
    float logit = gsum / (nq * nk) * temp[h];

    float m = logit;
#pragma unroll
    for (int o = 8; o > 0; o >>= 1)
        m = fmaxf(m, __shfl_xor_sync(0xffffffffu, m, o));
    float ex = expf(logit - m);
    float s = ex;
#pragma unroll
    for (int o = 8; o > 0; o >>= 1)
        s += __shfl_xor_sync(0xffffffffu, s, o);

    g_attn[bh * 256 + t] = ex / s;
}

// ---------------- out = attn @ v  -> y channels 0..127 (4n per thread) ------
__global__ void __launch_bounds__(256) av_k()
{
    const int bh = blockIdx.y;
    const int b  = bh >> 3, h = bh & 7;
    const int n  = blockIdx.x * 1024 + threadIdx.x * 4;

    __shared__ float As[256];
    As[threadIdx.x] = g_attn[bh * 256 + threadIdx.x];
    __syncthreads();

    const float* vp = g_qkv + ((size_t)b * 384 + 256 + h * 16) * HW + n;
    float acc[16][4];
#pragma unroll
    for (int dd = 0; dd < 16; dd++)
#pragma unroll
        for (int c = 0; c < 4; c++) acc[dd][c] = 0.f;

#pragma unroll
    for (int e = 0; e < 16; e++) {
        const float4 v4 = *(const float4*)(vp + (size_t)e * HW);
#pragma unroll
        for (int dd = 0; dd < 16; dd++) {
            const float w = As[dd * 16 + e];
            acc[dd][0] += w * v4.x;
            acc[dd][1] += w * v4.y;
            acc[dd][2] += w * v4.z;
            acc[dd][3] += w * v4.w;
        }
    }
    float* yp = g_y + ((size_t)b * 256 + h * 16) * HW + n;
#pragma unroll
    for (int dd = 0; dd < 16; dd++)
        *(float4*)(yp + (size_t)dd * HW) =
            make_float4(acc[dd][0], acc[dd][1], acc[dd][2], acc[dd][3]);
}

// ---------------- launcher ---------------------------------------------------
extern "C" void kernel_launch(void* const* d_in, const int* in_sizes, int n_in,
                              void* d_out, int out_size)
{
    const float* x      = (const float*)d_in[0];
    const float* pos_w  = (const float*)d_in[1];
    const float* pos_b  = (const float*)d_in[2];
    const float* qd3_w  = (const float*)d_in[3];
    const float* qd3_b  = (const float*)d_in[4];
    const float* qd5_w  = (const float*)d_in[5];
    const float* qd5_b  = (const float*)d_in[6];
    const float* temp   = (const float*)d_in[7];
    const float* d3_w   = (const float*)d_in[8];
    const float* d3_b   = (const float*)d_in[9];
    const float* d5_w   = (const float*)d_in[10];
    const float* d5_b   = (const float*)d_in[11];
    const float* proj_w = (const float*)d_in[12];
    float* out = (float*)d_out;

    // 1) t = pos 1x1 conv:  (384,128) @ x
    gemm_mma<384, 128, 0><<<dim3(HW / 128, 3, Bc), 256>>>(pos_w, x, pos_b, nullptr);

    // 2) qkv = concat(qd3(t), qd5(t))
    dualconv<0><<<dim3(16, 192, Bc), 256>>>(nullptr, qd3_w, qd3_b, qd5_w, qd5_b);

    // 3) gram partials + fused ssq, 8 n-chunks
    gram_k<<<dim3(64, 8), 256>>>();

    // 4) normalize + temperature + softmax -> attn
    softmax_k<<<64, 256>>>(temp);

    // 5) y[0:128] = attn @ v
    av_k<<<dim3(HW / 1024, 64), 256>>>();

    // 6) y[128:256] = concat(d3(x), d5(x))
    dualconv<1><<<dim3(16, 64, Bc), 256>>>(x, d3_w, d3_b, d5_w, d5_b);

    // 7) result = proj 1x1 conv: (128,256) @ y
    gemm_mma<128, 256, 1><<<dim3(HW / 128, 1, Bc), 256>>>(proj_w, nullptr, nullptr, out);
}